// round 16
// baseline (speedup 1.0000x reference)
#include <cuda_runtime.h>
#include <cuda_bf16.h>
#include <cstdint>

#define CC 256
#define NN 4096
#define BB 8

// ---------------- device globals (no runtime allocs allowed) ----------------
static __device__ __nv_bfloat16 g_Ah[CC * CC];      // A hi  [d][c]
static __device__ __nv_bfloat16 g_Al[CC * CC];      // A lo
static __device__ __nv_bfloat16 g_Xt_hi[(size_t)BB * NN * CC];  // X^T hi [b][n][c]
static __device__ __nv_bfloat16 g_Xt_lo[(size_t)BB * NN * CC];
static __device__ __nv_bfloat16 g_Zt_hi[(size_t)BB * NN * CC];  // Z^T hi [b][n][d]
static __device__ __nv_bfloat16 g_Zt_lo[(size_t)BB * NN * CC];
// split-softmax partials: [(b*64+nt)*4+mq][64 rows]
static __device__ float g_pm[(size_t)BB * 64 * 4 * 64];
static __device__ float g_ps[(size_t)BB * 64 * 4 * 64];
static __device__ float g_dlog[(size_t)BB * 64 * 64];

// ---------------- helpers ----------------
__device__ __forceinline__ float fexp2(float x) {
    float y;
    asm("ex2.approx.ftz.f32 %0, %1;" : "=f"(y) : "f"(x));
    return y;
}
__device__ __forceinline__ uint32_t smem_u32(const void* p) {
    uint32_t a;
    asm("{ .reg .u64 t; cvta.to.shared.u64 t, %1; cvt.u32.u64 %0, t; }" : "=r"(a) : "l"(p));
    return a;
}
#define SWZ(o) ((o) ^ (((o) >> 3) & 0x70))
// 64-byte-row swizzle: 8 consecutive rows hit 8 distinct 16B banks
#define SWZ64(r, c) ((c) ^ ((((r) >> 1) & 3) << 4))

#define CP16(dst, src) \
    asm volatile("cp.async.cg.shared.global [%0], [%1], 16;" :: "r"(dst), "l"(src) : "memory")
#define CP_COMMIT() asm volatile("cp.async.commit_group;" ::: "memory")
#define CP_WAIT0()  asm volatile("cp.async.wait_group 0;" ::: "memory")

__device__ __forceinline__ void ldsm4(uint32_t* r, uint32_t a) {
    asm volatile("ldmatrix.sync.aligned.m8n8.x4.shared.b16 {%0,%1,%2,%3}, [%4];"
        : "=r"(r[0]), "=r"(r[1]), "=r"(r[2]), "=r"(r[3]) : "r"(a));
}
__device__ __forceinline__ void mma16816(float* d, const uint32_t* a, const uint32_t* b) {
    asm volatile("mma.sync.aligned.m16n8k16.row.col.f32.bf16.bf16.f32 "
        "{%0,%1,%2,%3}, {%4,%5,%6,%7}, {%8,%9}, {%0,%1,%2,%3};"
        : "+f"(d[0]), "+f"(d[1]), "+f"(d[2]), "+f"(d[3])
        : "r"(a[0]), "r"(a[1]), "r"(a[2]), "r"(a[3]), "r"(b[0]), "r"(b[1]));
}
__device__ __forceinline__ uint32_t pack_bf16x2(__nv_bfloat16 a, __nv_bfloat16 b) {
    return (uint32_t)__bfloat16_as_ushort(a) | ((uint32_t)__bfloat16_as_ushort(b) << 16);
}

// ---------------------------------------------------------------------------
// k_prepA (smem-tiled): A[d][c] = log2e * sum_e Wq[e][c] * Wk[e][d]
// ---------------------------------------------------------------------------
__global__ __launch_bounds__(256) void k_prepA(const float* __restrict__ Wq,
                                               const float* __restrict__ Wk) {
    __shared__ float sq[64][33];
    __shared__ float sk[64][33];
    const float LOG2E = 1.4426950408889634f;
    const int tid = threadIdx.x;
    const int tx = tid & 31, tg = tid >> 5;
    const int c0 = blockIdx.x * 32, d0 = blockIdx.y * 32;

    float s[4] = {0.f, 0.f, 0.f, 0.f};
#pragma unroll 1
    for (int kc = 0; kc < CC; kc += 64) {
        __syncthreads();
#pragma unroll
        for (int t = 0; t < 8; t++) {
            int o = tid + t * 256;
            int e = o >> 5, cl = o & 31;
            sq[e][cl] = Wq[(kc + e) * CC + c0 + cl];
            sk[e][cl] = Wk[(kc + e) * CC + d0 + cl];
        }
        __syncthreads();
#pragma unroll 8
        for (int e = 0; e < 64; e++) {
            float q = sq[e][tx];
#pragma unroll
            for (int i = 0; i < 4; i++)
                s[i] = fmaf(q, sk[e][tg + 8 * i], s[i]);
        }
    }
#pragma unroll
    for (int i = 0; i < 4; i++) {
        float v = s[i] * LOG2E;
        __nv_bfloat16 h = __float2bfloat16(v);
        int d = d0 + tg + 8 * i;
        g_Ah[d * CC + c0 + tx] = h;
        g_Al[d * CC + c0 + tx] = __float2bfloat16(v - __bfloat162float(h));
    }
}

// ---------------------------------------------------------------------------
// Transpose + bf16 hi/lo split: X[b][c][n] -> Xt_hi/lo[b][n][c]
// ---------------------------------------------------------------------------
__global__ __launch_bounds__(256) void k_prep(const float* __restrict__ X) {
    __shared__ float s[32][33];
    const int b = blockIdx.z, c0 = blockIdx.y * 32, n0 = blockIdx.x * 32;
    const int tx = threadIdx.x, ty = threadIdx.y;
    const float* Xb = X + (size_t)b * CC * NN;
#pragma unroll
    for (int i = 0; i < 4; i++)
        s[ty + 8 * i][tx] = Xb[(size_t)(c0 + ty + 8 * i) * NN + n0 + tx];
    __syncthreads();
    const size_t base = (size_t)b * NN * CC;
#pragma unroll
    for (int i = 0; i < 4; i++) {
        int n = n0 + ty + 8 * i;
        float v = s[tx][ty + 8 * i];
        __nv_bfloat16 h = __float2bfloat16(v);
        g_Xt_hi[base + (size_t)n * CC + c0 + tx] = h;
        g_Xt_lo[base + (size_t)n * CC + c0 + tx] =
            __float2bfloat16(v - __bfloat162float(h));
    }
}

// ---------------------------------------------------------------------------
// k_Zt (512-thread 4x4 microkernel): Zt[n][d] = sum_c Xt[n][c] * A[d][c]
// ---------------------------------------------------------------------------
__global__ __launch_bounds__(512, 1) void k_Zt() {
    extern __shared__ char smem[];
    const uint32_t sb = smem_u32(smem);
    const int tid = threadIdx.x;
    const int wid = tid >> 5, lane = tid & 31;
    const int wr = wid >> 2, wc = wid & 3;
    const int n0 = blockIdx.x << 7;
    const int d0 = blockIdx.y << 7;
    const int b = blockIdx.z;
    const size_t bbase = (size_t)b * NN * CC;
    const char* Xsrc[2] = {(const char*)(g_Xt_hi + bbase), (const char*)(g_Xt_lo + bbase)};
    const char* Asrc[2] = {(const char*)g_Ah, (const char*)g_Al};

    const int aColX = (lane >> 4) << 4;
    const int bRowOff = (lane & 7) + ((lane >> 4) & 1) * 8;
    const int bColX = ((lane >> 3) & 1) << 4;

    float acc[2][4][4];
#pragma unroll
    for (int i = 0; i < 2; i++)
#pragma unroll
        for (int j = 0; j < 4; j++)
#pragma unroll
            for (int k = 0; k < 4; k++) acc[i][j][k] = 0.f;

#pragma unroll
    for (int t = 0; t < 8; t++) {
        int o = tid + t * 512;
        int role = o >> 10, r = (o >> 3) & 127, j = o & 7;
        const char* src = (role < 2)
            ? Xsrc[role] + ((size_t)(n0 + r) * CC) * 2 + j * 16
            : Asrc[role - 2] + ((size_t)(d0 + r) * CC) * 2 + j * 16;
        uint32_t dst = sb + (uint32_t)role * 16384u + SWZ((uint32_t)(r * 128 + j * 16));
        CP16(dst, src);
    }
    CP_COMMIT();

#pragma unroll 1
    for (int cc = 0; cc < 4; cc++) {
        const int buf = cc & 1;
        CP_WAIT0();
        __syncthreads();
        if (cc < 3) {
            const int cn = cc + 1, bn = buf ^ 1;
#pragma unroll
            for (int t = 0; t < 8; t++) {
                int o = tid + t * 512;
                int role = o >> 10, r = (o >> 3) & 127, j = o & 7;
                const char* src = (role < 2)
                    ? Xsrc[role] + ((size_t)(n0 + r) * CC + cn * 64) * 2 + j * 16
                    : Asrc[role - 2] + ((size_t)(d0 + r) * CC + cn * 64) * 2 + j * 16;
                uint32_t dst = sb + (uint32_t)bn * 65536u + (uint32_t)role * 16384u +
                               SWZ((uint32_t)(r * 128 + j * 16));
                CP16(dst, src);
            }
        }
        CP_COMMIT();

        const uint32_t xh = sb + (uint32_t)buf * 65536u;
        const uint32_t xl = xh + 16384u;
        const uint32_t ah = xh + 32768u;
        const uint32_t al = xh + 49152u;
#pragma unroll
        for (int ks = 0; ks < 4; ks++) {
            const int cb = ks * 32;
            uint32_t Ah[2][4], Al[2][4], Bh[2][4], Bl[2][4];
#pragma unroll
            for (int rb = 0; rb < 2; rb++) {
                int row = wr * 32 + rb * 16 + (lane & 15);
                uint32_t off = (uint32_t)(row * 128) +
                               (uint32_t)((cb + aColX) ^ ((row * 16) & 0x70));
                ldsm4(Ah[rb], xh + off);
                ldsm4(Al[rb], xl + off);
            }
#pragma unroll
            for (int cs = 0; cs < 2; cs++) {
                int row = wc * 32 + cs * 16 + bRowOff;
                uint32_t off = (uint32_t)(row * 128) +
                               (uint32_t)((cb + bColX) ^ ((row * 16) & 0x70));
                ldsm4(Bh[cs], ah + off);
                ldsm4(Bl[cs], al + off);
            }
#pragma unroll
            for (int rb = 0; rb < 2; rb++)
#pragma unroll
                for (int cs = 0; cs < 2; cs++) {
                    mma16816(acc[rb][cs * 2],     Ah[rb], Bh[cs]);
                    mma16816(acc[rb][cs * 2 + 1], Ah[rb], Bh[cs] + 2);
                }
#pragma unroll
            for (int rb = 0; rb < 2; rb++)
#pragma unroll
                for (int cs = 0; cs < 2; cs++) {
                    mma16816(acc[rb][cs * 2],     Ah[rb], Bl[cs]);
                    mma16816(acc[rb][cs * 2 + 1], Ah[rb], Bl[cs] + 2);
                }
#pragma unroll
            for (int rb = 0; rb < 2; rb++)
#pragma unroll
                for (int cs = 0; cs < 2; cs++) {
                    mma16816(acc[rb][cs * 2],     Al[rb], Bh[cs]);
                    mma16816(acc[rb][cs * 2 + 1], Al[rb], Bh[cs] + 2);
                }
        }
    }

    char* Zh = (char*)(g_Zt_hi + bbase);
    char* Zl = (char*)(g_Zt_lo + bbase);
#pragma unroll
    for (int rb = 0; rb < 2; rb++)
#pragma unroll
        for (int h = 0; h < 2; h++) {
            int n = n0 + wr * 32 + rb * 16 + h * 8 + (lane >> 2);
#pragma unroll
            for (int j = 0; j < 4; j++) {
                float v0 = acc[rb][j][2 * h], v1 = acc[rb][j][2 * h + 1];
                __nv_bfloat16 h0 = __float2bfloat16(v0);
                __nv_bfloat16 h1 = __float2bfloat16(v1);
                __nv_bfloat16 l0 = __float2bfloat16(v0 - __bfloat162float(h0));
                __nv_bfloat16 l1 = __float2bfloat16(v1 - __bfloat162float(h1));
                size_t off = ((size_t)n * CC + d0 + wc * 32 + j * 8 + 2 * (lane & 3)) * 2;
                *(uint32_t*)(Zh + off) = pack_bf16x2(h0, h1);
                *(uint32_t*)(Zl + off) = pack_bf16x2(l0, l1);
            }
        }
}

// ---------------------------------------------------------------------------
// k_part (R15: 2 CTAs/SM): CTA tile 64 n-rows x 128 m-cols, 256 threads,
// 8 warps 2x4 (warp tile 32x32). Z persistent (64KB SW128). X double-
// buffered K=32 chunks (2 x 16KB, 64B rows with SWZ64). grid B*64*4.
// Cross-CTA interleave on each SM overlaps one CTA's MMA phase with the
// other's LDSM phase (breaking the phase-adding convoy measured at 55%).
// ---------------------------------------------------------------------------
#define SM_ZS 0u
#define SM_XS 65536u
#define SM_TOTAL (65536 + 2 * 16384)

__global__ __launch_bounds__(256, 2) void k_part() {
    extern __shared__ char smem[];
    const uint32_t sb = smem_u32(smem);
    const int tid = threadIdx.x;
    const int wid = tid >> 5, lane = tid & 31;
    const int wr = wid >> 2, wc = wid & 3;     // 2x4 warp grid
    const int g = lane >> 2;
    const int bx = blockIdx.x;
    const int b = bx >> 8;
    const int nt = (bx >> 2) & 63;             // 64-row n tile
    const int mq = bx & 3;
    const int n0 = nt << 6;
    const size_t bbase = (size_t)b * NN * CC;
    const char* Zsrc[2] = {(const char*)(g_Zt_hi + bbase), (const char*)(g_Zt_lo + bbase)};
    const char* Xsrc[2] = {(const char*)(g_Xt_hi + bbase), (const char*)(g_Xt_lo + bbase)};

    const int aColX = (lane >> 4) << 4;
    const int bRowOff = (lane & 7) + ((lane >> 4) & 1) * 8;
    const int bColX = ((lane >> 3) & 1) << 4;

    // ---- prologue: Z (8 tiles of 64rows x 64K, SW128) ----
#pragma unroll
    for (int t = 0; t < 16; t++) {
        int o = tid + t * 256;
        int ch = o >> 10, hs = (o >> 9) & 1, rem = o & 511;
        int r = rem >> 3, j = rem & 7;
        const char* src = Zsrc[hs] + ((size_t)(n0 + r) * CC + ch * 64) * 2 + j * 16;
        uint32_t dst = sb + SM_ZS + (uint32_t)(ch * 2 + hs) * 8192u +
                       SWZ((uint32_t)(r * 128 + j * 16));
        CP16(dst, src);
    }
    // ---- X chunk 0 into buffer 0 ----
    {
        const int m00 = mq * 1024;
#pragma unroll
        for (int t = 0; t < 4; t++) {
            int o = tid + t * 256;
            int hs = o >> 9, rem = o & 511, r = rem >> 2, cq = (rem & 3) << 4;
            const char* src = Xsrc[hs] + ((size_t)(m00 + r) * CC) * 2 + cq;
            uint32_t dst = sb + SM_XS + (uint32_t)hs * 8192u +
                           (uint32_t)(r * 64 + SWZ64(r, cq));
            CP16(dst, src);
        }
        CP_COMMIT();
    }

    float acc[2][4][4];
#pragma unroll
    for (int i = 0; i < 2; i++)
#pragma unroll
        for (int j = 0; j < 4; j++)
#pragma unroll
            for (int k = 0; k < 4; k++) acc[i][j][k] = 0.f;
    float mrun[2][2], rsum[2][2];
#pragma unroll
    for (int i = 0; i < 2; i++)
#pragma unroll
        for (int j = 0; j < 2; j++) { mrun[i][j] = -3.0e38f; rsum[i][j] = 0.f; }

#pragma unroll 1
    for (int G = 0; G < 64; G++) {
        const int kc = G & 7, mtl = G >> 3, buf = G & 1;
        CP_WAIT0();          // chunk G (the only pending group) has landed
        __syncthreads();     // all warps done reading chunk G-1 (buf^1)

        // producer AFTER sync: chunk G+1 into buf^1 (WAR-safe)
        if (G < 63) {
            const int Gn = G + 1;
            const int kcn = Gn & 7, m0n = mq * 1024 + (Gn >> 3) * 128;
#pragma unroll
            for (int t = 0; t < 4; t++) {
                int o = tid + t * 256;
                int hs = o >> 9, rem = o & 511, r = rem >> 2, cq = (rem & 3) << 4;
                const char* src = Xsrc[hs] + ((size_t)(m0n + r) * CC) * 2 + kcn * 64 + cq;
                uint32_t dst = sb + SM_XS + (uint32_t)(buf ^ 1) * 16384u +
                               (uint32_t)hs * 8192u + (uint32_t)(r * 64 + SWZ64(r, cq));
                CP16(dst, src);
            }
        }
        CP_COMMIT();

        const uint32_t zb = sb + SM_ZS + (uint32_t)(kc >> 1) * 16384u;  // hi; lo=+8192
        const uint32_t xb = sb + SM_XS + (uint32_t)buf * 16384u;        // hi; lo=+8192
        const int cbz0 = (kc & 1) * 64;
#pragma unroll
        for (int ks = 0; ks < 2; ks++) {
            const int cb = cbz0 + ks * 32;
            const int cx = ks * 32;
            uint32_t Ah[2][4], Al[2][4], Bh[2][4], Bl[2][4];
#pragma unroll
            for (int rb = 0; rb < 2; rb++) {
                int row = wr * 32 + rb * 16 + (lane & 15);
                uint32_t off = (uint32_t)(row * 128) +
                               (uint32_t)((cb + aColX) ^ ((row * 16) & 0x70));
                ldsm4(Ah[rb], zb + off);
                ldsm4(Al[rb], zb + 8192u + off);
            }
            {
                int row = wc * 32 + 0 * 16 + bRowOff;
                uint32_t off = (uint32_t)(row * 64) + (uint32_t)SWZ64(row, cx + bColX);
                ldsm4(Bh[0], xb + off);
                ldsm4(Bl[0], xb + 8192u + off);
            }
#pragma unroll
            for (int rb = 0; rb < 2; rb++) {
                mma16816(acc[rb][0], Ah[rb], Bh[0]);
                mma16816(acc[rb][1], Ah[rb], Bh[0] + 2);
            }
#pragma unroll
            for (int rb = 0; rb < 2; rb++) {
                mma16816(acc[rb][0], Ah[rb], Bl[0]);
                mma16816(acc[rb][1], Ah[rb], Bl[0] + 2);
            }
            {
                int row = wc * 32 + 1 * 16 + bRowOff;
                uint32_t off = (uint32_t)(row * 64) + (uint32_t)SWZ64(row, cx + bColX);
                ldsm4(Bh[1], xb + off);
                ldsm4(Bl[1], xb + 8192u + off);
            }
#pragma unroll
            for (int rb = 0; rb < 2; rb++) {
                mma16816(acc[rb][0], Al[rb], Bh[0]);
                mma16816(acc[rb][1], Al[rb], Bh[0] + 2);
            }
#pragma unroll
            for (int rb = 0; rb < 2; rb++) {
                mma16816(acc[rb][2], Ah[rb], Bh[1]);
                mma16816(acc[rb][3], Ah[rb], Bh[1] + 2);
            }
#pragma unroll
            for (int rb = 0; rb < 2; rb++) {
                mma16816(acc[rb][2], Ah[rb], Bl[1]);
                mma16816(acc[rb][3], Ah[rb], Bl[1] + 2);
            }
#pragma unroll
            for (int rb = 0; rb < 2; rb++) {
                mma16816(acc[rb][2], Al[rb], Bh[1]);
                mma16816(acc[rb][3], Al[rb], Bh[1] + 2);
            }
        }

        // ---- m-tile boundary (every 8 chunks): online softmax ----
        if (kc == 7) {
            __syncthreads();   // all warps past their ldsm of buf
            float* pmax = (float*)(smem + SM_XS + (uint32_t)buf * 16384u);
            float* psum = pmax + 256;

#pragma unroll
            for (int rb = 0; rb < 2; rb++)
#pragma unroll
                for (int rh = 0; rh < 2; rh++) {
                    float tm = -3.0e38f;
#pragma unroll
                    for (int j = 0; j < 4; j++)
                        tm = fmaxf(tm, fmaxf(acc[rb][j][2 * rh], acc[rb][j][2 * rh + 1]));
                    tm = fmaxf(tm, __shfl_xor_sync(0xffffffffu, tm, 1));
                    tm = fmaxf(tm, __shfl_xor_sync(0xffffffffu, tm, 2));
                    float ps = 0.f;
#pragma unroll
                    for (int j = 0; j < 4; j++) {
                        ps += fexp2(acc[rb][j][2 * rh] - tm);
                        ps += fexp2(acc[rb][j][2 * rh + 1] - tm);
                    }
                    ps += __shfl_xor_sync(0xffffffffu, ps, 1);
                    ps += __shfl_xor_sync(0xffffffffu, ps, 2);
                    if ((lane & 3) == 0) {
                        int rl = wr * 32 + rb * 16 + rh * 8 + g;
                        pmax[wc * 64 + rl] = tm;
                        psum[wc * 64 + rl] = ps;
                    }
                }
            // diag: global col nt*64+rl lives here iff mq==nt>>4, mtl==(nt>>1)&7;
            // within tile: wc == (nt&1)*2 + wr, fragment lane&3 == g>>1.
            if (mq == (nt >> 4) && mtl == ((nt >> 1) & 7) &&
                wc == ((nt & 1) * 2 + wr) && (lane & 3) == (g >> 1)) {
#pragma unroll
                for (int rb = 0; rb < 2; rb++)
#pragma unroll
                    for (int rh = 0; rh < 2; rh++) {
                        int rl = wr * 32 + rb * 16 + rh * 8 + g;
                        g_dlog[(size_t)(b * 64 + nt) * 64 + rl] =
                            acc[rb][rb * 2 + rh][(rh << 1) | (g & 1)];
                    }
            }
            __syncthreads();
            // replicated combine across 4 wc partials
#pragma unroll
            for (int rb = 0; rb < 2; rb++)
#pragma unroll
                for (int rh = 0; rh < 2; rh++) {
                    int rl = wr * 32 + rb * 16 + rh * 8 + g;
                    float mn = mrun[rb][rh];
#pragma unroll
                    for (int j = 0; j < 4; j++) mn = fmaxf(mn, pmax[j * 64 + rl]);
                    float rs = rsum[rb][rh] * fexp2(mrun[rb][rh] - mn);
#pragma unroll
                    for (int j = 0; j < 4; j++)
                        rs += fexp2(pmax[j * 64 + rl] - mn) * psum[j * 64 + rl];
                    mrun[rb][rh] = mn;
                    rsum[rb][rh] = rs;
                }
#pragma unroll
            for (int i = 0; i < 2; i++)
#pragma unroll
                for (int j = 0; j < 4; j++)
#pragma unroll
                    for (int k = 0; k < 4; k++) acc[i][j][k] = 0.f;
        }
    }

    // write partial state
    if (wc == 0 && (lane & 3) == 0) {
#pragma unroll
        for (int rb = 0; rb < 2; rb++)
#pragma unroll
            for (int rh = 0; rh < 2; rh++) {
                int rl = wr * 32 + rb * 16 + rh * 8 + g;
                g_pm[(size_t)bx * 64 + rl] = mrun[rb][rh];
                g_ps[(size_t)bx * 64 + rl] = rsum[rb][rh];
            }
    }
}

// ---------------------------------------------------------------------------
// k_final: combine 4 partials -> diag (64 rows); out = X * diag
// grid B*64, 512 threads
// ---------------------------------------------------------------------------
__global__ __launch_bounds__(512) void k_final(const float* __restrict__ X,
                                               float* __restrict__ out) {
    __shared__ float sdiag[64];
    const int bx = blockIdx.x;
    const int b = bx >> 6, nt = bx & 63;
    const int n0 = nt << 6;
    const int tid = threadIdx.x;

    if (tid < 64) {
        float pm[4];
        float M = -3.0e38f;
#pragma unroll
        for (int q = 0; q < 4; q++) {
            pm[q] = g_pm[((size_t)bx * 4 + q) * 64 + tid];
            M = fmaxf(M, pm[q]);
        }
        float S = 0.f;
#pragma unroll
        for (int q = 0; q < 4; q++)
            S += g_ps[((size_t)bx * 4 + q) * 64 + tid] * fexp2(pm[q] - M);
        sdiag[tid] = fexp2(g_dlog[(size_t)bx * 64 + tid] - M) / S *
                     (1.0f / (1.0f + 1e-8f));
    }
    __syncthreads();

    const float* Xb = X + (size_t)b * CC * NN;
    float* Ob = out + (size_t)b * CC * NN;
#pragma unroll 4
    for (int t = 0; t < 8; t++) {
        int f = tid + t * 512;
        int row = f >> 4;
        int c4 = (f & 15) << 2;
        float4 v = *(const float4*)&Xb[(size_t)row * NN + n0 + c4];
        float4 dv = *(const float4*)&sdiag[c4];
        v.x *= dv.x; v.y *= dv.y; v.z *= dv.z; v.w *= dv.w;
        *(float4*)&Ob[(size_t)row * NN + n0 + c4] = v;
    }
}

// ---------------------------------------------------------------------------
extern "C" void kernel_launch(void* const* d_in, const int* in_sizes, int n_in,
                              void* d_out, int out_size) {
    const float* X  = (const float*)d_in[0];
    const float* Wq = (const float*)d_in[1];
    const float* Wk = (const float*)d_in[2];
    float* out = (float*)d_out;

    cudaFuncSetAttribute(k_Zt, cudaFuncAttributeMaxDynamicSharedMemorySize, 131072);
    cudaFuncSetAttribute(k_part, cudaFuncAttributeMaxDynamicSharedMemorySize, SM_TOTAL);

    k_prepA<<<dim3(8, 8), 256>>>(Wq, Wk);
    k_prep<<<dim3(NN / 32, CC / 32, BB), dim3(32, 8)>>>(X);
    k_Zt<<<dim3(32, 2, BB), 512, 131072>>>();
    k_part<<<BB * 64 * 4, 256, SM_TOTAL>>>();
    k_final<<<BB * 64, 512>>>(X, out);
}